// round 10
// baseline (speedup 1.0000x reference)
#include <cuda_runtime.h>
#include <cuda_fp16.h>
#include <cstdint>

#define NN 100000
#define EE 3200000
#define NC 64
#define TOPK 16
#define NHID 128
#define DEG 6
#define SCAN_BS 1024
#define SCAN_NB ((NN + SCAN_BS - 1) / SCAN_BS)   // 98

// ---------------- device scratch (static allocation only) ----------------
__device__ int   g_count[NN];            // zero at load; self-restored each call
__device__ int   g_rowstart[NN + 1];
__device__ int   g_cursor[NN];
__device__ int   g_aggr[SCAN_NB];
__device__ int   g_incl[SCAN_NB];
__device__ int   g_flag[SCAN_NB];
__device__ __align__(16) int2 g_csr[EE]; // (col, val bits fp32)
__device__ __align__(16) __half g_curh[5][(size_t)NN * NC];
__device__ float g_weight[NN * DEG];
__device__ float g_W1T[TOPK * NHID];     // transposed W1: [k][r]

// ---------------- hist (+ reset scan flags for this call) ----------------
__global__ void k_hist(const int* __restrict__ er) {
    int i = blockIdx.x * blockDim.x + threadIdx.x;
    if (i < SCAN_NB) g_flag[i] = 0;
    if (i < EE) atomicAdd(&g_count[er[i]], 1);
}

// ---------------- prep: transpose W1 (8KB, trivial) ----------------
__global__ void k_prep(const float* __restrict__ W1) {
    int i = threadIdx.x + blockIdx.x * blockDim.x;
    if (i < NHID * TOPK) {
        int r = i / TOPK, k = i % TOPK;
        g_W1T[k * NHID + r] = W1[i];
    }
}

// ------- single-pass scan (decoupled lookback), pure CSR offsets -------
__global__ void __launch_bounds__(SCAN_BS) k_scan() {
    __shared__ int sh[SCAN_BS];
    __shared__ int s_prefix;
    int b = blockIdx.x, t = threadIdx.x;
    int i = b * SCAN_BS + t;

    int v = (i < NN) ? g_count[i] : 0;
    if (i < NN) g_count[i] = 0;
    sh[t] = v;
    __syncthreads();
    for (int o = 1; o < SCAN_BS; o <<= 1) {
        int tt = (t >= o) ? sh[t - o] : 0;
        __syncthreads();
        sh[t] += tt;
        __syncthreads();
    }
    int total = sh[SCAN_BS - 1];

    if (t == 0) {
        g_aggr[b] = total;
        __threadfence();
        g_flag[b] = 1;
        int pfx = 0;
        for (int j = b - 1; j >= 0; j--) {
            int f;
            do { f = ((volatile int*)g_flag)[j]; } while (f == 0);
            if (f == 2) { pfx += ((volatile int*)g_incl)[j]; break; }
            pfx += ((volatile int*)g_aggr)[j];
        }
        g_incl[b] = pfx + total;
        __threadfence();
        g_flag[b] = 2;
        s_prefix = pfx;
        if (b == 0) g_rowstart[NN] = EE;
    }
    __syncthreads();

    if (i < NN) {
        int r = s_prefix + sh[t] - v;
        g_rowstart[i] = r;
        g_cursor[i]   = r;
    }
}

// ------- gating: smem weights, softmax -> bitonic top16 -> MLP -> weights -------
__global__ void __launch_bounds__(512) k_gating(const float* __restrict__ x,
                                                const float* __restrict__ b1,
                                                const float* __restrict__ W2,
                                                const float* __restrict__ b2) {
    __shared__ float sW1[TOPK * NHID];   // 8KB
    __shared__ float sW2[DEG * NHID];    // 3KB
    {
        int t = threadIdx.x;
        #pragma unroll
        for (int i = t; i < TOPK * NHID; i += 512) sW1[i] = g_W1T[i];
        for (int i = t; i < DEG * NHID; i += 512)  sW2[i] = W2[i];
    }
    __syncthreads();

    int warp = (blockIdx.x * blockDim.x + threadIdx.x) >> 5;
    if (warp >= NN) return;
    int lane = threadIdx.x & 31;

    float2 xv = *(const float2*)(x + (size_t)warp * NC + 2 * lane);

    // softmax over 64
    float m = fmaxf(xv.x, xv.y);
    #pragma unroll
    for (int o = 16; o; o >>= 1) m = fmaxf(m, __shfl_xor_sync(~0u, m, o));
    float e0 = __expf(xv.x - m), e1 = __expf(xv.y - m);
    float s = e0 + e1;
    #pragma unroll
    for (int o = 16; o; o >>= 1) s += __shfl_xor_sync(~0u, s, o);
    float inv = 1.0f / s;
    float a = e0 * inv, b = e1 * inv;

    // bitonic sort of 64 values, descending (values only)
    #pragma unroll
    for (int k = 2; k <= 64; k <<= 1) {
        #pragma unroll
        for (int j = k >> 1; j > 0; j >>= 1) {
            if (j >= 2) {
                float pa = __shfl_xor_sync(~0u, a, j >> 1);
                float pb = __shfl_xor_sync(~0u, b, j >> 1);
                int i0 = 2 * lane, i1 = 2 * lane + 1;
                bool up  = ((i0 & k) != 0);
                bool km0 = (((i0 & j) == 0) != up);
                bool km1 = (((i1 & j) == 0) != up);
                a = km0 ? fmaxf(a, pa) : fminf(a, pa);
                b = km1 ? fmaxf(b, pb) : fminf(b, pb);
            } else {
                bool up = (((2 * lane) & k) != 0);
                float mx = fmaxf(a, b), mn = fminf(a, b);
                a = up ? mn : mx;
                b = up ? mx : mn;
            }
        }
    }

    // broadcast top-16 (vidx 0..15 live in lanes 0..7)
    float tk[TOPK];
    #pragma unroll
    for (int q = 0; q < 8; q++) {
        tk[2 * q]     = __shfl_sync(~0u, a, q);
        tk[2 * q + 1] = __shfl_sync(~0u, b, q);
    }

    // layer 1: smem weights, stride-1 conflict-free
    float h[4];
    #pragma unroll
    for (int j = 0; j < 4; j++) h[j] = b1[lane + 32 * j];
    #pragma unroll
    for (int k = 0; k < TOPK; k++) {
        #pragma unroll
        for (int j = 0; j < 4; j++)
            h[j] += tk[k] * sW1[k * NHID + lane + 32 * j];
    }
    #pragma unroll
    for (int j = 0; j < 4; j++) h[j] = (h[j] >= 0.0f) ? h[j] : 0.1f * h[j];

    // layer 2
    float lg[DEG];
    #pragma unroll
    for (int d = 0; d < DEG; d++) {
        float acc = 0.0f;
        #pragma unroll
        for (int j = 0; j < 4; j++) acc += h[j] * sW2[d * NHID + lane + 32 * j];
        #pragma unroll
        for (int o = 16; o; o >>= 1) acc += __shfl_xor_sync(~0u, acc, o);
        lg[d] = acc + b2[d];
    }

    // softmax over 6 hops
    float mm = lg[0];
    #pragma unroll
    for (int d = 1; d < DEG; d++) mm = fmaxf(mm, lg[d]);
    float ss = 0.0f;
    #pragma unroll
    for (int d = 0; d < DEG; d++) { lg[d] = __expf(lg[d] - mm); ss += lg[d]; }
    float invs = 1.0f / ss;
    if (lane < DEG) g_weight[warp * DEG + lane] = lg[lane] * invs;
}

// ---------------- scatter ----------------
__global__ void k_scatter(const int* __restrict__ er,
                          const int* __restrict__ ec,
                          const float* __restrict__ ev) {
    int i = blockIdx.x * blockDim.x + threadIdx.x;
    if (i >= EE) return;
    int pos = atomicAdd(&g_cursor[er[i]], 1);
    g_csr[pos] = make_int2(ec[i], __float_as_int(ev[i]));
}

// -------- SpMM hop 0: warp-per-row, gather fp32 x, fp32 accum, fp16 store --------
__global__ void __launch_bounds__(256) k_spmm0(const float* __restrict__ x) {
    int row = (blockIdx.x * blockDim.x + threadIdx.x) >> 5;
    if (row >= NN) return;
    int lane = threadIdx.x & 31;

    int s = g_rowstart[row], e = g_rowstart[row + 1];
    float ax = 0.0f, ay = 0.0f;

    int i = s;
    for (; i + 4 <= e; i += 4) {
        int2 e0 = __ldg(&g_csr[i]);
        int2 e1 = __ldg(&g_csr[i + 1]);
        int2 e2 = __ldg(&g_csr[i + 2]);
        int2 e3 = __ldg(&g_csr[i + 3]);
        float2 f0 = *(const float2*)(x + (size_t)e0.x * NC + 2 * lane);
        float2 f1 = *(const float2*)(x + (size_t)e1.x * NC + 2 * lane);
        float2 f2 = *(const float2*)(x + (size_t)e2.x * NC + 2 * lane);
        float2 f3 = *(const float2*)(x + (size_t)e3.x * NC + 2 * lane);
        float v0 = __int_as_float(e0.y), v1 = __int_as_float(e1.y);
        float v2 = __int_as_float(e2.y), v3 = __int_as_float(e3.y);
        ax += v0 * f0.x + v1 * f1.x + v2 * f2.x + v3 * f3.x;
        ay += v0 * f0.y + v1 * f1.y + v2 * f2.y + v3 * f3.y;
    }
    for (; i < e; i++) {
        int2 e0 = __ldg(&g_csr[i]);
        float2 f0 = *(const float2*)(x + (size_t)e0.x * NC + 2 * lane);
        float v0 = __int_as_float(e0.y);
        ax += v0 * f0.x;
        ay += v0 * f0.y;
    }

    *(__half2*)(g_curh[0] + (size_t)row * NC + 2 * lane) = __floats2half2_rn(ax, ay);
}

// -------- SpMM hops 1-4: warp-per-row, fp16 gather, HFMA2 accum --------
__global__ void __launch_bounds__(256) k_spmm(int srcsel, int dstsel) {
    int row = (blockIdx.x * blockDim.x + threadIdx.x) >> 5;
    if (row >= NN) return;
    int lane = threadIdx.x & 31;

    const __half* __restrict__ cur = g_curh[srcsel];
    __half* __restrict__ next = g_curh[dstsel];

    int s = g_rowstart[row], e = g_rowstart[row + 1];
    __half2 acc = __floats2half2_rn(0.f, 0.f);

    int i = s;
    for (; i + 4 <= e; i += 4) {
        int2 e0 = __ldg(&g_csr[i]);
        int2 e1 = __ldg(&g_csr[i + 1]);
        int2 e2 = __ldg(&g_csr[i + 2]);
        int2 e3 = __ldg(&g_csr[i + 3]);
        __half2 f0 = *(const __half2*)(cur + (size_t)e0.x * NC + 2 * lane);
        __half2 f1 = *(const __half2*)(cur + (size_t)e1.x * NC + 2 * lane);
        __half2 f2 = *(const __half2*)(cur + (size_t)e2.x * NC + 2 * lane);
        __half2 f3 = *(const __half2*)(cur + (size_t)e3.x * NC + 2 * lane);
        acc = __hfma2(f0, __float2half2_rn(__int_as_float(e0.y)), acc);
        acc = __hfma2(f1, __float2half2_rn(__int_as_float(e1.y)), acc);
        acc = __hfma2(f2, __float2half2_rn(__int_as_float(e2.y)), acc);
        acc = __hfma2(f3, __float2half2_rn(__int_as_float(e3.y)), acc);
    }
    for (; i < e; i++) {
        int2 e0 = __ldg(&g_csr[i]);
        __half2 f0 = *(const __half2*)(cur + (size_t)e0.x * NC + 2 * lane);
        acc = __hfma2(f0, __float2half2_rn(__int_as_float(e0.y)), acc);
    }

    *(__half2*)(next + (size_t)row * NC + 2 * lane) = acc;
}

// ------- final: out = w0*x + sum_h w_h*cur_h, then log_softmax -------
__global__ void k_final(const float* __restrict__ x, float* __restrict__ dout) {
    int warp = (blockIdx.x * blockDim.x + threadIdx.x) >> 5;
    if (warp >= NN) return;
    int lane = threadIdx.x & 31;
    size_t off = (size_t)warp * NC + 2 * lane;

    float w[DEG];
    #pragma unroll
    for (int d = 0; d < DEG; d++) w[d] = __ldg(&g_weight[warp * DEG + d]);

    float2 xv = *(const float2*)(x + off);
    float tx = w[0] * xv.x, ty = w[0] * xv.y;
    #pragma unroll
    for (int h = 0; h < 5; h++) {
        float2 c = __half22float2(*(const __half2*)(g_curh[h] + off));
        tx += w[h + 1] * c.x;
        ty += w[h + 1] * c.y;
    }

    float m = fmaxf(tx, ty);
    #pragma unroll
    for (int o = 16; o; o >>= 1) m = fmaxf(m, __shfl_xor_sync(~0u, m, o));
    float s = __expf(tx - m) + __expf(ty - m);
    #pragma unroll
    for (int o = 16; o; o >>= 1) s += __shfl_xor_sync(~0u, s, o);
    float l = m + __logf(s);
    *(float2*)(dout + off) = make_float2(tx - l, ty - l);
}

// ---------------- launch ----------------
extern "C" void kernel_launch(void* const* d_in, const int* in_sizes, int n_in,
                              void* d_out, int out_size) {
    const float* x  = (const float*)d_in[0];
    const int*   er = (const int*)d_in[1];
    const int*   ec = (const int*)d_in[2];
    const float* ev = (const float*)d_in[3];
    const float* W1 = (const float*)d_in[4];
    const float* b1 = (const float*)d_in[5];
    const float* W2 = (const float*)d_in[6];
    const float* b2 = (const float*)d_in[7];
    float* out = (float*)d_out;

    k_hist<<<(EE + 255) / 256, 256>>>(er);                        // idx 0
    k_prep<<<8, 256>>>(W1);                                       // idx 1
    k_scan<<<SCAN_NB, SCAN_BS>>>();                               // idx 2
    k_gating<<<(NN * 32 + 511) / 512, 512>>>(x, b1, W2, b2);      // idx 3 <- profiled
    k_scatter<<<(EE + 255) / 256, 256>>>(er, ec, ev);             // idx 4

    k_spmm0<<<(NN * 32 + 255) / 256, 256>>>(x);                   // idx 5
    k_spmm<<<(NN * 32 + 255) / 256, 256>>>(0, 1);                 // idx 6
    k_spmm<<<(NN * 32 + 255) / 256, 256>>>(1, 2);                 // idx 7
    k_spmm<<<(NN * 32 + 255) / 256, 256>>>(2, 3);                 // idx 8
    k_spmm<<<(NN * 32 + 255) / 256, 256>>>(3, 4);                 // idx 9

    k_final<<<(NN * 32 + 255) / 256, 256>>>(x, out);              // idx 10
}

// round 11
// speedup vs baseline: 1.2905x; 1.2905x over previous
#include <cuda_runtime.h>
#include <cuda_fp16.h>
#include <cstdint>

#define NN 100000
#define EE 3200000
#define NC 64
#define TOPK 16
#define NHID 128
#define DEG 6
#define SCAN_BS 1024
#define SCAN_NB ((NN + SCAN_BS - 1) / SCAN_BS)   // 98

// ---------------- device scratch (static allocation only) ----------------
__device__ int   g_count[NN];            // zero at load; self-restored each call
__device__ int   g_rowstart[NN + 1];
__device__ int   g_cursor[NN];
__device__ int   g_aggr[SCAN_NB];
__device__ int   g_incl[SCAN_NB];
__device__ int   g_flag[SCAN_NB];
__device__ __align__(16) int2 g_csr[EE]; // (col, val bits fp32)
__device__ __align__(16) __half g_xh[(size_t)NN * NC];
__device__ __align__(16) __half g_curh[5][(size_t)NN * NC];
__device__ float g_weight[NN * DEG];
__device__ float g_W1T[TOPK * NHID];     // transposed W1: [k][r]

// ---------------- prep: transpose W1 (8KB, trivial) ----------------
__global__ void k_prep(const float* __restrict__ W1) {
    int i = threadIdx.x + blockIdx.x * blockDim.x;
    if (i < NHID * TOPK) {
        int r = i / TOPK, k = i % TOPK;
        g_W1T[k * NHID + r] = W1[i];
    }
}

// ---------------- hist (+ reset scan flags for this call) ----------------
__global__ void k_hist(const int* __restrict__ er) {
    int i = blockIdx.x * blockDim.x + threadIdx.x;
    if (i < SCAN_NB) g_flag[i] = 0;
    if (i < EE) atomicAdd(&g_count[er[i]], 1);
}

// ------- single-pass scan (decoupled lookback), pure CSR offsets -------
__global__ void __launch_bounds__(SCAN_BS) k_scan() {
    __shared__ int sh[SCAN_BS];
    __shared__ int s_prefix;
    int b = blockIdx.x, t = threadIdx.x;
    int i = b * SCAN_BS + t;

    int v = (i < NN) ? g_count[i] : 0;
    if (i < NN) g_count[i] = 0;
    sh[t] = v;
    __syncthreads();
    for (int o = 1; o < SCAN_BS; o <<= 1) {
        int tt = (t >= o) ? sh[t - o] : 0;
        __syncthreads();
        sh[t] += tt;
        __syncthreads();
    }
    int total = sh[SCAN_BS - 1];

    if (t == 0) {
        g_aggr[b] = total;
        __threadfence();
        g_flag[b] = 1;
        int pfx = 0;
        for (int j = b - 1; j >= 0; j--) {
            int f;
            do { f = ((volatile int*)g_flag)[j]; } while (f == 0);
            if (f == 2) { pfx += ((volatile int*)g_incl)[j]; break; }
            pfx += ((volatile int*)g_aggr)[j];
        }
        g_incl[b] = pfx + total;
        __threadfence();
        g_flag[b] = 2;
        s_prefix = pfx;
        if (b == 0) g_rowstart[NN] = EE;
    }
    __syncthreads();

    if (i < NN) {
        int r = s_prefix + sh[t] - v;
        g_rowstart[i] = r;
        g_cursor[i]   = r;
    }
}

// ------- gating: softmax -> bitonic top16 -> MLP (coalesced W1T) -> weights
//         + fused x -> fp16 emit (gating already reads all of x) -------
__global__ void k_gating(const float* __restrict__ x,
                         const float* __restrict__ b1,
                         const float* __restrict__ W2, const float* __restrict__ b2) {
    int warp = (blockIdx.x * blockDim.x + threadIdx.x) >> 5;
    if (warp >= NN) return;
    int lane = threadIdx.x & 31;

    float2 xv = *(const float2*)(x + (size_t)warp * NC + 2 * lane);

    // fp16 copy of x for hop-0 gather
    *(__half2*)(g_xh + (size_t)warp * NC + 2 * lane) = __floats2half2_rn(xv.x, xv.y);

    // softmax over 64
    float m = fmaxf(xv.x, xv.y);
    #pragma unroll
    for (int o = 16; o; o >>= 1) m = fmaxf(m, __shfl_xor_sync(~0u, m, o));
    float e0 = __expf(xv.x - m), e1 = __expf(xv.y - m);
    float s = e0 + e1;
    #pragma unroll
    for (int o = 16; o; o >>= 1) s += __shfl_xor_sync(~0u, s, o);
    float inv = 1.0f / s;
    float a = e0 * inv, b = e1 * inv;   // vidx 2*lane, 2*lane+1

    // bitonic sort of 64 values, descending (values only)
    #pragma unroll
    for (int k = 2; k <= 64; k <<= 1) {
        #pragma unroll
        for (int j = k >> 1; j > 0; j >>= 1) {
            if (j >= 2) {
                float pa = __shfl_xor_sync(~0u, a, j >> 1);
                float pb = __shfl_xor_sync(~0u, b, j >> 1);
                int i0 = 2 * lane, i1 = 2 * lane + 1;
                bool up  = ((i0 & k) != 0);
                bool km0 = (((i0 & j) == 0) != up);
                bool km1 = (((i1 & j) == 0) != up);
                a = km0 ? fmaxf(a, pa) : fminf(a, pa);
                b = km1 ? fmaxf(b, pb) : fminf(b, pb);
            } else {
                bool up = (((2 * lane) & k) != 0);
                float mx = fmaxf(a, b), mn = fminf(a, b);
                a = up ? mn : mx;
                b = up ? mx : mn;
            }
        }
    }

    // broadcast top-16 (vidx 0..15 live in lanes 0..7)
    float tk[TOPK];
    #pragma unroll
    for (int q = 0; q < 8; q++) {
        tk[2 * q]     = __shfl_sync(~0u, a, q);
        tk[2 * q + 1] = __shfl_sync(~0u, b, q);
    }

    // layer 1: coalesced W1T reads (lane-consecutive addresses)
    float h[4];
    #pragma unroll
    for (int j = 0; j < 4; j++) h[j] = b1[lane + 32 * j];
    #pragma unroll
    for (int k = 0; k < TOPK; k++) {
        #pragma unroll
        for (int j = 0; j < 4; j++)
            h[j] += tk[k] * __ldg(&g_W1T[k * NHID + lane + 32 * j]);
    }
    #pragma unroll
    for (int j = 0; j < 4; j++) h[j] = (h[j] >= 0.0f) ? h[j] : 0.1f * h[j];

    // layer 2 (already coalesced)
    float lg[DEG];
    #pragma unroll
    for (int d = 0; d < DEG; d++) {
        float acc = 0.0f;
        #pragma unroll
        for (int j = 0; j < 4; j++) acc += h[j] * __ldg(&W2[d * NHID + lane + 32 * j]);
        #pragma unroll
        for (int o = 16; o; o >>= 1) acc += __shfl_xor_sync(~0u, acc, o);
        lg[d] = acc + b2[d];
    }

    // softmax over 6 hops
    float mm = lg[0];
    #pragma unroll
    for (int d = 1; d < DEG; d++) mm = fmaxf(mm, lg[d]);
    float ss = 0.0f;
    #pragma unroll
    for (int d = 0; d < DEG; d++) { lg[d] = __expf(lg[d] - mm); ss += lg[d]; }
    float invs = 1.0f / ss;
    if (lane < DEG) g_weight[warp * DEG + lane] = lg[lane] * invs;
}

// ---------------- scatter ----------------
__global__ void k_scatter(const int* __restrict__ er,
                          const int* __restrict__ ec,
                          const float* __restrict__ ev) {
    int i = blockIdx.x * blockDim.x + threadIdx.x;
    if (i >= EE) return;
    int pos = atomicAdd(&g_cursor[er[i]], 1);
    g_csr[pos] = make_int2(ec[i], __float_as_int(ev[i]));
}

// -------- SpMM gather: fp16 features, HFMA2 fp16 accumulation (R9 layout) --------
__device__ __forceinline__ void mach(__half2* acc, uint4 raw, __half2 vh) {
    acc[0] = __hfma2(*(__half2*)&raw.x, vh, acc[0]);
    acc[1] = __hfma2(*(__half2*)&raw.y, vh, acc[1]);
    acc[2] = __hfma2(*(__half2*)&raw.z, vh, acc[2]);
    acc[3] = __hfma2(*(__half2*)&raw.w, vh, acc[3]);
}

__global__ void __launch_bounds__(256) k_spmm(int srcsel, int dstsel) {
    int gtid = blockIdx.x * blockDim.x + threadIdx.x;
    int row = gtid >> 3;                 // 8 lanes per row
    if (row >= NN) return;
    int sub = threadIdx.x & 7;

    const __half* __restrict__ cur = (srcsel < 0) ? g_xh : g_curh[srcsel];
    __half* __restrict__ next = g_curh[dstsel];

    int s = g_rowstart[row], e = g_rowstart[row + 1];
    __half2 acc[4];
    #pragma unroll
    for (int j = 0; j < 4; j++) acc[j] = __floats2half2_rn(0.f, 0.f);

    int i = s;
    if ((i & 1) && i < e) {              // peel to 16B boundary for int4 csr loads
        int2 e0 = __ldg(&g_csr[i]);
        uint4 r0 = *(const uint4*)(cur + (size_t)e0.x * NC + sub * 8);
        mach(acc, r0, __float2half2_rn(__int_as_float(e0.y)));
        i++;
    }
    for (; i + 8 <= e; i += 8) {
        int4 p0 = __ldg((const int4*)&g_csr[i]);
        int4 p1 = __ldg((const int4*)&g_csr[i + 2]);
        int4 p2 = __ldg((const int4*)&g_csr[i + 4]);
        int4 p3 = __ldg((const int4*)&g_csr[i + 6]);
        uint4 r0 = *(const uint4*)(cur + (size_t)p0.x * NC + sub * 8);
        uint4 r1 = *(const uint4*)(cur + (size_t)p0.z * NC + sub * 8);
        uint4 r2 = *(const uint4*)(cur + (size_t)p1.x * NC + sub * 8);
        uint4 r3 = *(const uint4*)(cur + (size_t)p1.z * NC + sub * 8);
        uint4 r4 = *(const uint4*)(cur + (size_t)p2.x * NC + sub * 8);
        uint4 r5 = *(const uint4*)(cur + (size_t)p2.z * NC + sub * 8);
        uint4 r6 = *(const uint4*)(cur + (size_t)p3.x * NC + sub * 8);
        uint4 r7 = *(const uint4*)(cur + (size_t)p3.z * NC + sub * 8);
        mach(acc, r0, __float2half2_rn(__int_as_float(p0.y)));
        mach(acc, r1, __float2half2_rn(__int_as_float(p0.w)));
        mach(acc, r2, __float2half2_rn(__int_as_float(p1.y)));
        mach(acc, r3, __float2half2_rn(__int_as_float(p1.w)));
        mach(acc, r4, __float2half2_rn(__int_as_float(p2.y)));
        mach(acc, r5, __float2half2_rn(__int_as_float(p2.w)));
        mach(acc, r6, __float2half2_rn(__int_as_float(p3.y)));
        mach(acc, r7, __float2half2_rn(__int_as_float(p3.w)));
    }
    for (; i < e; i++) {
        int2 e0 = __ldg(&g_csr[i]);
        uint4 r0 = *(const uint4*)(cur + (size_t)e0.x * NC + sub * 8);
        mach(acc, r0, __float2half2_rn(__int_as_float(e0.y)));
    }

    size_t off = (size_t)row * NC + sub * 8;
    uint4 packed;
    __half2* ph = (__half2*)&packed;
    ph[0] = acc[0]; ph[1] = acc[1]; ph[2] = acc[2]; ph[3] = acc[3];
    *(uint4*)(next + off) = packed;
}

// ------- final: out = w0*x + sum_h w_h*cur_h, then log_softmax -------
__global__ void k_final(const float* __restrict__ x, float* __restrict__ dout) {
    int warp = (blockIdx.x * blockDim.x + threadIdx.x) >> 5;
    if (warp >= NN) return;
    int lane = threadIdx.x & 31;
    size_t off = (size_t)warp * NC + 2 * lane;

    float w[DEG];
    #pragma unroll
    for (int d = 0; d < DEG; d++) w[d] = __ldg(&g_weight[warp * DEG + d]);

    float2 xv = *(const float2*)(x + off);
    float tx = w[0] * xv.x, ty = w[0] * xv.y;
    #pragma unroll
    for (int h = 0; h < 5; h++) {
        float2 c = __half22float2(*(const __half2*)(g_curh[h] + off));
        tx += w[h + 1] * c.x;
        ty += w[h + 1] * c.y;
    }

    float m = fmaxf(tx, ty);
    #pragma unroll
    for (int o = 16; o; o >>= 1) m = fmaxf(m, __shfl_xor_sync(~0u, m, o));
    float s = __expf(tx - m) + __expf(ty - m);
    #pragma unroll
    for (int o = 16; o; o >>= 1) s += __shfl_xor_sync(~0u, s, o);
    float l = m + __logf(s);
    *(float2*)(dout + off) = make_float2(tx - l, ty - l);
}

// ---------------- launch ----------------
extern "C" void kernel_launch(void* const* d_in, const int* in_sizes, int n_in,
                              void* d_out, int out_size) {
    const float* x  = (const float*)d_in[0];
    const int*   er = (const int*)d_in[1];
    const int*   ec = (const int*)d_in[2];
    const float* ev = (const float*)d_in[3];
    const float* W1 = (const float*)d_in[4];
    const float* b1 = (const float*)d_in[5];
    const float* W2 = (const float*)d_in[6];
    const float* b2 = (const float*)d_in[7];
    float* out = (float*)d_out;

    k_prep<<<8, 256>>>(W1);                                       // idx 0
    k_hist<<<(EE + 255) / 256, 256>>>(er);                        // idx 1
    k_scan<<<SCAN_NB, SCAN_BS>>>();                               // idx 2
    k_gating<<<(NN * 32 + 255) / 256, 256>>>(x, b1, W2, b2);      // idx 3 <- profiled
    k_scatter<<<(EE + 255) / 256, 256>>>(er, ec, ev);             // idx 4

    k_spmm<<<(NN * 8 + 255) / 256, 256>>>(-1, 0);                 // idx 5
    k_spmm<<<(NN * 8 + 255) / 256, 256>>>(0, 1);                  // idx 6
    k_spmm<<<(NN * 8 + 255) / 256, 256>>>(1, 2);                  // idx 7
    k_spmm<<<(NN * 8 + 255) / 256, 256>>>(2, 3);                  // idx 8
    k_spmm<<<(NN * 8 + 255) / 256, 256>>>(3, 4);                  // idx 9

    k_final<<<(NN * 32 + 255) / 256, 256>>>(x, out);              // idx 10
}

// round 12
// speedup vs baseline: 1.3709x; 1.0623x over previous
#include <cuda_runtime.h>
#include <cuda_fp16.h>
#include <cstdint>

#define NN 100000
#define EE 3200000
#define NC 64
#define TOPK 16
#define NHID 128
#define DEG 6
#define SCAN_BS 1024
#define SCAN_NB ((NN + SCAN_BS - 1) / SCAN_BS)   // 98

// ---------------- device scratch (static allocation only) ----------------
__device__ int   g_count[NN];            // zero at load; self-restored each call
__device__ int   g_rowstart[NN + 1];
__device__ int   g_cursor[NN];
__device__ int   g_aggr[SCAN_NB];
__device__ int   g_incl[SCAN_NB];
__device__ int   g_flag[SCAN_NB];
__device__ __align__(16) int2 g_csr[EE]; // (col, val bits fp32)
__device__ __align__(16) __half g_xh[(size_t)NN * NC];
__device__ __align__(16) __half g_curh[4][(size_t)NN * NC];
__device__ float g_weight[NN * DEG];
__device__ __half2 g_W1h[TOPK * (NHID / 2)];  // [k][unit-pair]
__device__ __half2 g_W2h[DEG * (NHID / 2)];   // [d][unit-pair]

// -------- prep: pack W1 (transposed) and W2 into half2 unit-pairs --------
// g_W1h[k*64 + j] = (W1[2j][k], W1[2j+1][k]);  g_W2h[d*64 + j] = (W2[d][2j], W2[d][2j+1])
__global__ void k_prep(const float* __restrict__ W1, const float* __restrict__ W2) {
    int i = threadIdx.x + blockIdx.x * blockDim.x;
    if (i < TOPK * (NHID / 2)) {
        int k = i / (NHID / 2), j = i % (NHID / 2);
        g_W1h[i] = __floats2half2_rn(W1[(2 * j) * TOPK + k], W1[(2 * j + 1) * TOPK + k]);
    }
    int q = i - TOPK * (NHID / 2);
    if (q >= 0 && q < DEG * (NHID / 2)) {
        int d = q / (NHID / 2), j = q % (NHID / 2);
        g_W2h[q] = __floats2half2_rn(W2[d * NHID + 2 * j], W2[d * NHID + 2 * j + 1]);
    }
}

// ---------------- hist (+ reset scan flags for this call) ----------------
__global__ void k_hist(const int* __restrict__ er) {
    int i = blockIdx.x * blockDim.x + threadIdx.x;
    if (i < SCAN_NB) g_flag[i] = 0;
    if (i < EE) atomicAdd(&g_count[er[i]], 1);
}

// ------- single-pass scan (decoupled lookback), pure CSR offsets -------
__global__ void __launch_bounds__(SCAN_BS) k_scan() {
    __shared__ int sh[SCAN_BS];
    __shared__ int s_prefix;
    int b = blockIdx.x, t = threadIdx.x;
    int i = b * SCAN_BS + t;

    int v = (i < NN) ? g_count[i] : 0;
    if (i < NN) g_count[i] = 0;
    sh[t] = v;
    __syncthreads();
    for (int o = 1; o < SCAN_BS; o <<= 1) {
        int tt = (t >= o) ? sh[t - o] : 0;
        __syncthreads();
        sh[t] += tt;
        __syncthreads();
    }
    int total = sh[SCAN_BS - 1];

    if (t == 0) {
        g_aggr[b] = total;
        __threadfence();
        g_flag[b] = 1;
        int pfx = 0;
        for (int j = b - 1; j >= 0; j--) {
            int f;
            do { f = ((volatile int*)g_flag)[j]; } while (f == 0);
            if (f == 2) { pfx += ((volatile int*)g_incl)[j]; break; }
            pfx += ((volatile int*)g_aggr)[j];
        }
        g_incl[b] = pfx + total;
        __threadfence();
        g_flag[b] = 2;
        s_prefix = pfx;
        if (b == 0) g_rowstart[NN] = EE;
    }
    __syncthreads();

    if (i < NN) {
        int r = s_prefix + sh[t] - v;
        g_rowstart[i] = r;
        g_cursor[i]   = r;
    }
}

// ------- gating: softmax -> bitonic top16 -> MLP (half2 weights) -> weights
//         + fused x -> fp16 emit -------
__global__ void k_gating(const float* __restrict__ x,
                         const float* __restrict__ b1,
                         const float* __restrict__ b2) {
    int warp = (blockIdx.x * blockDim.x + threadIdx.x) >> 5;
    if (warp >= NN) return;
    int lane = threadIdx.x & 31;

    float2 xv = *(const float2*)(x + (size_t)warp * NC + 2 * lane);
    *(__half2*)(g_xh + (size_t)warp * NC + 2 * lane) = __floats2half2_rn(xv.x, xv.y);

    // softmax over 64
    float m = fmaxf(xv.x, xv.y);
    #pragma unroll
    for (int o = 16; o; o >>= 1) m = fmaxf(m, __shfl_xor_sync(~0u, m, o));
    float e0 = __expf(xv.x - m), e1 = __expf(xv.y - m);
    float s = e0 + e1;
    #pragma unroll
    for (int o = 16; o; o >>= 1) s += __shfl_xor_sync(~0u, s, o);
    float inv = 1.0f / s;
    float a = e0 * inv, b = e1 * inv;

    // bitonic sort of 64 values, descending (values only)
    #pragma unroll
    for (int k = 2; k <= 64; k <<= 1) {
        #pragma unroll
        for (int j = k >> 1; j > 0; j >>= 1) {
            if (j >= 2) {
                float pa = __shfl_xor_sync(~0u, a, j >> 1);
                float pb = __shfl_xor_sync(~0u, b, j >> 1);
                int i0 = 2 * lane, i1 = 2 * lane + 1;
                bool up  = ((i0 & k) != 0);
                bool km0 = (((i0 & j) == 0) != up);
                bool km1 = (((i1 & j) == 0) != up);
                a = km0 ? fmaxf(a, pa) : fminf(a, pa);
                b = km1 ? fmaxf(b, pb) : fminf(b, pb);
            } else {
                bool up = (((2 * lane) & k) != 0);
                float mx = fmaxf(a, b), mn = fminf(a, b);
                a = up ? mn : mx;
                b = up ? mx : mn;
            }
        }
    }

    // broadcast top-16
    float tk[TOPK];
    #pragma unroll
    for (int q = 0; q < 8; q++) {
        tk[2 * q]     = __shfl_sync(~0u, a, q);
        tk[2 * q + 1] = __shfl_sync(~0u, b, q);
    }

    // layer 1: lane owns hidden units {2l, 2l+1, 64+2l, 65+2l}; fp32 accum
    float h[4];
    {
        float2 ba = *(const float2*)(b1 + 2 * lane);
        float2 bb = *(const float2*)(b1 + 64 + 2 * lane);
        h[0] = ba.x; h[1] = ba.y; h[2] = bb.x; h[3] = bb.y;
    }
    #pragma unroll
    for (int k = 0; k < TOPK; k++) {
        float tkk = tk[k];
        float2 fa = __half22float2(__ldg(&g_W1h[k * 64 + lane]));
        float2 fb = __half22float2(__ldg(&g_W1h[k * 64 + 32 + lane]));
        h[0] += tkk * fa.x; h[1] += tkk * fa.y;
        h[2] += tkk * fb.x; h[3] += tkk * fb.y;
    }
    #pragma unroll
    for (int j = 0; j < 4; j++) h[j] = (h[j] >= 0.0f) ? h[j] : 0.1f * h[j];

    // layer 2
    float lg[DEG];
    #pragma unroll
    for (int d = 0; d < DEG; d++) {
        float2 fa = __half22float2(__ldg(&g_W2h[d * 64 + lane]));
        float2 fb = __half22float2(__ldg(&g_W2h[d * 64 + 32 + lane]));
        float acc = h[0] * fa.x + h[1] * fa.y + h[2] * fb.x + h[3] * fb.y;
        #pragma unroll
        for (int o = 16; o; o >>= 1) acc += __shfl_xor_sync(~0u, acc, o);
        lg[d] = acc + b2[d];
    }

    // softmax over 6 hops
    float mm = lg[0];
    #pragma unroll
    for (int d = 1; d < DEG; d++) mm = fmaxf(mm, lg[d]);
    float ss = 0.0f;
    #pragma unroll
    for (int d = 0; d < DEG; d++) { lg[d] = __expf(lg[d] - mm); ss += lg[d]; }
    float invs = 1.0f / ss;
    if (lane < DEG) g_weight[warp * DEG + lane] = lg[lane] * invs;
}

// ---------------- scatter ----------------
__global__ void k_scatter(const int* __restrict__ er,
                          const int* __restrict__ ec,
                          const float* __restrict__ ev) {
    int i = blockIdx.x * blockDim.x + threadIdx.x;
    if (i >= EE) return;
    int pos = atomicAdd(&g_cursor[er[i]], 1);
    g_csr[pos] = make_int2(ec[i], __float_as_int(ev[i]));
}

// -------- SpMM gather core: fp16 features, HFMA2, 4 acc chains --------
__device__ __forceinline__ void mach(__half2* acc, uint4 raw, __half2 vh) {
    acc[0] = __hfma2(*(__half2*)&raw.x, vh, acc[0]);
    acc[1] = __hfma2(*(__half2*)&raw.y, vh, acc[1]);
    acc[2] = __hfma2(*(__half2*)&raw.z, vh, acc[2]);
    acc[3] = __hfma2(*(__half2*)&raw.w, vh, acc[3]);
}

__device__ __forceinline__ void spmm_row(const __half* __restrict__ cur,
                                         int s, int e, int sub, __half2* acc) {
    int i = s;
    if ((i & 1) && i < e) {
        int2 e0 = __ldg(&g_csr[i]);
        uint4 r0 = *(const uint4*)(cur + (size_t)e0.x * NC + sub * 8);
        mach(acc, r0, __float2half2_rn(__int_as_float(e0.y)));
        i++;
    }
    for (; i + 8 <= e; i += 8) {
        int4 p0 = __ldg((const int4*)&g_csr[i]);
        int4 p1 = __ldg((const int4*)&g_csr[i + 2]);
        int4 p2 = __ldg((const int4*)&g_csr[i + 4]);
        int4 p3 = __ldg((const int4*)&g_csr[i + 6]);
        uint4 r0 = *(const uint4*)(cur + (size_t)p0.x * NC + sub * 8);
        uint4 r1 = *(const uint4*)(cur + (size_t)p0.z * NC + sub * 8);
        uint4 r2 = *(const uint4*)(cur + (size_t)p1.x * NC + sub * 8);
        uint4 r3 = *(const uint4*)(cur + (size_t)p1.z * NC + sub * 8);
        uint4 r4 = *(const uint4*)(cur + (size_t)p2.x * NC + sub * 8);
        uint4 r5 = *(const uint4*)(cur + (size_t)p2.z * NC + sub * 8);
        uint4 r6 = *(const uint4*)(cur + (size_t)p3.x * NC + sub * 8);
        uint4 r7 = *(const uint4*)(cur + (size_t)p3.z * NC + sub * 8);
        mach(acc, r0, __float2half2_rn(__int_as_float(p0.y)));
        mach(acc, r1, __float2half2_rn(__int_as_float(p0.w)));
        mach(acc, r2, __float2half2_rn(__int_as_float(p1.y)));
        mach(acc, r3, __float2half2_rn(__int_as_float(p1.w)));
        mach(acc, r4, __float2half2_rn(__int_as_float(p2.y)));
        mach(acc, r5, __float2half2_rn(__int_as_float(p2.w)));
        mach(acc, r6, __float2half2_rn(__int_as_float(p3.y)));
        mach(acc, r7, __float2half2_rn(__int_as_float(p3.w)));
    }
    for (; i < e; i++) {
        int2 e0 = __ldg(&g_csr[i]);
        uint4 r0 = *(const uint4*)(cur + (size_t)e0.x * NC + sub * 8);
        mach(acc, r0, __float2half2_rn(__int_as_float(e0.y)));
    }
}

__global__ void __launch_bounds__(256) k_spmm(int srcsel, int dstsel) {
    int gtid = blockIdx.x * blockDim.x + threadIdx.x;
    int row = gtid >> 3;                 // 8 lanes per row; grid exact
    int sub = threadIdx.x & 7;

    const __half* __restrict__ cur = (srcsel < 0) ? g_xh : g_curh[srcsel];
    __half* __restrict__ next = g_curh[dstsel];

    __half2 acc[4];
    #pragma unroll
    for (int j = 0; j < 4; j++) acc[j] = __floats2half2_rn(0.f, 0.f);

    spmm_row(cur, g_rowstart[row], g_rowstart[row + 1], sub, acc);

    size_t off = (size_t)row * NC + sub * 8;
    uint4 packed;
    __half2* ph = (__half2*)&packed;
    ph[0] = acc[0]; ph[1] = acc[1]; ph[2] = acc[2]; ph[3] = acc[3];
    *(uint4*)(next + off) = packed;
}

// ---- last hop fused with output: out = w0*x + sum_h w_h*cur_h, log_softmax ----
__global__ void __launch_bounds__(256) k_spmm_last(const float* __restrict__ x,
                                                   float* __restrict__ dout) {
    int gtid = blockIdx.x * blockDim.x + threadIdx.x;
    int row = gtid >> 3;                 // grid exact: no early exit, full-mask shfl OK
    int sub = threadIdx.x & 7;

    __half2 acc[4];
    #pragma unroll
    for (int j = 0; j < 4; j++) acc[j] = __floats2half2_rn(0.f, 0.f);

    spmm_row(g_curh[3], g_rowstart[row], g_rowstart[row + 1], sub, acc);

    // epilogue: weighted sum in fp32
    size_t off = (size_t)row * NC + sub * 8;
    float w[DEG];
    #pragma unroll
    for (int d = 0; d < DEG; d++) w[d] = __ldg(&g_weight[row * DEG + d]);

    float o[8];
    {
        float4 x0 = *(const float4*)(x + off);
        float4 x1 = *(const float4*)(x + off + 4);
        o[0] = w[0] * x0.x; o[1] = w[0] * x0.y; o[2] = w[0] * x0.z; o[3] = w[0] * x0.w;
        o[4] = w[0] * x1.x; o[5] = w[0] * x1.y; o[6] = w[0] * x1.z; o[7] = w[0] * x1.w;
    }
    #pragma unroll
    for (int h = 0; h < 4; h++) {
        uint4 raw = *(const uint4*)(g_curh[h] + off);
        float2 f0 = __half22float2(*(__half2*)&raw.x);
        float2 f1 = __half22float2(*(__half2*)&raw.y);
        float2 f2 = __half22float2(*(__half2*)&raw.z);
        float2 f3 = __half22float2(*(__half2*)&raw.w);
        float wh = w[h + 1];
        o[0] += wh * f0.x; o[1] += wh * f0.y; o[2] += wh * f1.x; o[3] += wh * f1.y;
        o[4] += wh * f2.x; o[5] += wh * f2.y; o[6] += wh * f3.x; o[7] += wh * f3.y;
    }
    // hop-5 term from registers
    #pragma unroll
    for (int j = 0; j < 4; j++) {
        float2 f = __half22float2(acc[j]);
        o[2 * j]     += w[5] * f.x;
        o[2 * j + 1] += w[5] * f.y;
    }

    // log_softmax across the 8-lane group (offsets 1,2,4 stay in-group)
    float m = o[0];
    #pragma unroll
    for (int j = 1; j < 8; j++) m = fmaxf(m, o[j]);
    #pragma unroll
    for (int t = 1; t < 8; t <<= 1) m = fmaxf(m, __shfl_xor_sync(~0u, m, t));
    float s = 0.0f;
    #pragma unroll
    for (int j = 0; j < 8; j++) s += __expf(o[j] - m);
    #pragma unroll
    for (int t = 1; t < 8; t <<= 1) s += __shfl_xor_sync(~0u, s, t);
    float l = m + __logf(s);

    float4 r0 = make_float4(o[0] - l, o[1] - l, o[2] - l, o[3] - l);
    float4 r1 = make_float4(o[4] - l, o[5] - l, o[6] - l, o[7] - l);
    *(float4*)(dout + off)     = r0;
    *(float4*)(dout + off + 4) = r1;
}

// ---------------- launch ----------------
extern "C" void kernel_launch(void* const* d_in, const int* in_sizes, int n_in,
                              void* d_out, int out_size) {
    const float* x  = (const float*)d_in[0];
    const int*   er = (const int*)d_in[1];
    const int*   ec = (const int*)d_in[2];
    const float* ev = (const float*)d_in[3];
    const float* W1 = (const float*)d_in[4];
    const float* b1 = (const float*)d_in[5];
    const float* W2 = (const float*)d_in[6];
    const float* b2 = (const float*)d_in[7];
    float* out = (float*)d_out;

    k_prep<<<8, 256>>>(W1, W2);                                   // idx 0
    k_hist<<<(EE + 255) / 256, 256>>>(er);                        // idx 1
    k_scan<<<SCAN_NB, SCAN_BS>>>();                               // idx 2
    k_gating<<<(NN * 32 + 255) / 256, 256>>>(x, b1, b2);          // idx 3 <- profiled
    k_scatter<<<(EE + 255) / 256, 256>>>(er, ec, ev);             // idx 4

    k_spmm<<<NN * 8 / 256, 256>>>(-1, 0);                         // idx 5
    k_spmm<<<NN * 8 / 256, 256>>>(0, 1);                          // idx 6
    k_spmm<<<NN * 8 / 256, 256>>>(1, 2);                          // idx 7
    k_spmm<<<NN * 8 / 256, 256>>>(2, 3);                          // idx 8
    k_spmm_last<<<NN * 8 / 256, 256>>>(x, out);                   // idx 9
}